// round 15
// baseline (speedup 1.0000x reference)
#include <cuda_runtime.h>
#include <cstdint>

// ---------------- problem constants ----------------
#define SEQA   4096
#define BATCH  8
#define DM     1024
#define NHEADS 16
#define HD     64
#define MROWS  (SEQA*BATCH)   // 32768

// ---------------- scratch (device globals; no allocation allowed) ----------
__device__ float g_Q[(size_t)MROWS * DM];
__device__ float g_K[(size_t)MROWS * DM];
__device__ float g_V[(size_t)MROWS * DM];
__device__ float g_X[(size_t)MROWS * DM];

// ---------------- helpers ----------------
__device__ __forceinline__ uint32_t f2tf32(float f) {
    uint32_t u;
    asm("cvt.rna.tf32.f32 %0, %1;" : "=r"(u) : "f"(f));
    return u;
}

__device__ __forceinline__ void mma_tf32(float c[4],
                                         uint32_t a0, uint32_t a1, uint32_t a2, uint32_t a3,
                                         uint32_t b0, uint32_t b1) {
    asm volatile(
        "mma.sync.aligned.m16n8k8.row.col.f32.tf32.tf32.f32 "
        "{%0,%1,%2,%3}, {%4,%5,%6,%7}, {%8,%9}, {%0,%1,%2,%3};"
        : "+f"(c[0]), "+f"(c[1]), "+f"(c[2]), "+f"(c[3])
        : "r"(a0), "r"(a1), "r"(a2), "r"(a3), "r"(b0), "r"(b1));
}

// ---------------- TF32 GEMM core: fragment-ordered smem ----------------
// Block 128x128, BK=32, 512 threads (16 warps), warp tile 32x32.
// Staging: LDG.128 -> cvt.rna.tf32 -> scattered STS into FRAGMENT ORDER so
// mainloop fragment loads are 2x LDS.128 (A) + 4x LDS.64 (B) per kk-step
// (round-14 ncu: 24 scalar LDS + 24 CVT per 16 MMA starved tensor pipe at
// 44.8% with occ 12.4%).
#define BM 128
#define BN 128
#define BK 32
#define TILE_FLOATS 4096               // 128x32
#define BUF_FLOATS  (2 * TILE_FLOATS)  // A + B per buffer
#define GEMM_SMEM   (2 * BUF_FLOATS * (int)sizeof(float))  // 65536 B

// A layout: off(m,k) = (((mreg*4+kkstep)*2+mi)*8+g)*16 + (tq^ (g&3) ^ mi)*4
//                      + half + 2*pair
//   mreg=m>>5, mi=(m>>4)&1, half=(m>>3)&1, g=m&7; kkstep=k>>3, pair=(k>>2)&1, tq=k&3
// B layout: off(n,k) = (((nreg*4+kkstep)*4+ni)*8+g)*8 + (tq ^ (g&3) ^ ni)*2 + pair
//   nreg=n>>5, ni=(n>>3)&3, g=n&7
// permute=0: C row = m ; permute=1: C row = (m&4095)*8 + (m>>12)
__device__ __forceinline__ void gemm_core(
    const float* __restrict__ A, const float* __restrict__ W,
    const float* __restrict__ bias, float* __restrict__ C, int permute)
{
    extern __shared__ float sm[];

    const int tid = threadIdx.x;
    const int wid = tid >> 5, lane = tid & 31;
    const int gid = lane >> 2, tq = lane & 3;
    const int wm = wid & 3;        // 4 M-regions of 32 rows
    const int wn = wid >> 2;       // 4 N-regions of 32 cols
    const int m0 = blockIdx.y * BM;
    const int n0 = blockIdx.x * BN;

    // ---- staging assignment: row = tid&127, k-chunk = (tid>>7)*8 ----
    const int srow = tid & 127;
    const int kk0 = tid >> 7;      // kkstep of this thread's chunk
    const int a_mreg = srow >> 5, a_mi = (srow >> 4) & 1;
    const int a_half = (srow >> 3) & 1, sg = srow & 7;
    const int b_ni = (srow >> 3) & 3;
    const int aBase = (((a_mreg * 4 + kk0) * 2 + a_mi) * 8 + sg) * 16;
    const int bBase = (((a_mreg * 4 + kk0) * 4 + b_ni) * 8 + sg) * 8;
    const int aSw = (sg & 3) ^ a_mi;
    const int bSw = (sg & 3) ^ b_ni;

    const float4* gA = (const float4*)(A + (size_t)(m0 + srow) * DM) + kk0 * 2;
    const float4* gB = (const float4*)(W + (size_t)(n0 + srow) * DM) + kk0 * 2;

    float acc[2][4][4];
#pragma unroll
    for (int i = 0; i < 2; i++)
#pragma unroll
        for (int j = 0; j < 4; j++)
#pragma unroll
            for (int k = 0; k < 4; k++) acc[i][j][k] = 0.f;

    float4 rA0 = gA[0], rA1 = gA[1];
    float4 rB0 = gB[0], rB1 = gB[1];

    const int NT = DM / BK;   // 32 tiles
    for (int t = 0; t < NT; t++) {
        uint32_t* dA = (uint32_t*)(sm + (t & 1) * BUF_FLOATS);
        uint32_t* dB = dA + TILE_FLOATS;

        // ---- scatter-store staged tile (fragment order, tf32-converted) ----
        {
            float va[8] = {rA0.x, rA0.y, rA0.z, rA0.w, rA1.x, rA1.y, rA1.z, rA1.w};
            float vb[8] = {rB0.x, rB0.y, rB0.z, rB0.w, rB1.x, rB1.y, rB1.z, rB1.w};
#pragma unroll
            for (int j = 0; j < 8; j++) {
                int pair = j >> 2, tqj = j & 3;
                dA[aBase + ((tqj ^ aSw) << 2) + a_half + (pair << 1)] = f2tf32(va[j]);
                dB[bBase + ((tqj ^ bSw) << 1) + pair]                 = f2tf32(vb[j]);
            }
        }
        __syncthreads();   // staged tile visible to all warps

        // prefetch next tile into registers (overlaps with MMA below)
        if (t + 1 < NT) {
            rA0 = gA[(t + 1) * 8];
            rA1 = gA[(t + 1) * 8 + 1];
            rB0 = gB[(t + 1) * 8];
            rB1 = gB[(t + 1) * 8 + 1];
        }

        const uint32_t* cA = (const uint32_t*)(sm + (t & 1) * BUF_FLOATS);
        const uint32_t* cB = cA + TILE_FLOATS;

#pragma unroll
        for (int k8 = 0; k8 < 4; k8++) {
            uint4 a[2];
            uint2 b[4];
#pragma unroll
            for (int mi = 0; mi < 2; mi++)
                a[mi] = *(const uint4*)(cA + wm * 1024 + k8 * 256 + mi * 128
                                        + gid * 16 + ((tq ^ (gid & 3) ^ mi) << 2));
#pragma unroll
            for (int ni = 0; ni < 4; ni++)
                b[ni] = *(const uint2*)(cB + wn * 1024 + k8 * 256 + ni * 64
                                        + gid * 8 + ((tq ^ (gid & 3) ^ ni) << 1));
#pragma unroll
            for (int mi = 0; mi < 2; mi++)
#pragma unroll
                for (int ni = 0; ni < 4; ni++)
                    mma_tf32(acc[mi][ni], a[mi].x, a[mi].y, a[mi].z, a[mi].w,
                             b[ni].x, b[ni].y);
        }
        // no second sync: STS(t+1) targets the other buffer (double-buffered)
    }

    // ---- epilogue: bias + optional row permutation ----
#pragma unroll
    for (int ni = 0; ni < 4; ni++) {
        int col = n0 + wn * 32 + ni * 8 + tq * 2;
        float bb0 = bias[col], bb1 = bias[col + 1];
#pragma unroll
        for (int mi = 0; mi < 2; mi++) {
            int row0 = m0 + wm * 32 + mi * 16 + gid;
            int row1 = row0 + 8;
            size_t or0 = permute ? (size_t)((row0 & 4095) * 8 + (row0 >> 12)) : (size_t)row0;
            size_t or1 = permute ? (size_t)((row1 & 4095) * 8 + (row1 >> 12)) : (size_t)row1;
            float2 v0 = make_float2(acc[mi][ni][0] + bb0, acc[mi][ni][1] + bb1);
            float2 v1 = make_float2(acc[mi][ni][2] + bb0, acc[mi][ni][3] + bb1);
            *(float2*)(C + or0 * DM + col) = v0;
            *(float2*)(C + or1 * DM + col) = v1;
        }
    }
}

// QKV projections in ONE launch: blockIdx.z selects the stream.
__global__ __launch_bounds__(512, 1) void gemm_qkv(
    const float* __restrict__ Aq, const float* __restrict__ Ak,
    const float* __restrict__ Av,
    const float* __restrict__ Wq, const float* __restrict__ Wk,
    const float* __restrict__ Wv,
    const float* __restrict__ bq, const float* __restrict__ bk,
    const float* __restrict__ bv,
    float* __restrict__ Cq, float* __restrict__ Ck, float* __restrict__ Cv)
{
    const int z = blockIdx.z;
    const float* A = (z == 0) ? Aq : (z == 1) ? Ak : Av;
    const float* W = (z == 0) ? Wq : (z == 1) ? Wk : Wv;
    const float* b = (z == 0) ? bq : (z == 1) ? bk : bv;
    float*       C = (z == 0) ? Cq : (z == 1) ? Ck : Cv;
    gemm_core(A, W, b, C, 0);
}

__global__ __launch_bounds__(512, 1) void gemm_out(
    const float* __restrict__ A, const float* __restrict__ W,
    const float* __restrict__ bias, float* __restrict__ C)
{
    gemm_core(A, W, bias, C, 1);
}

// ---------------- per-position head-mixing attention + sparsemax ------------
#define APAD 68   // floats per row: float4-aligned

__global__ __launch_bounds__(256) void attn_kernel(
    const float* __restrict__ Q, const float* __restrict__ K,
    const float* __restrict__ V, float* __restrict__ X)
{
    const int pos = blockIdx.x;            // pos = a*BATCH + b
    const int a = pos >> 3, b = pos & 7;
    const int tid = threadIdx.x;

    __shared__ float Qs[NHEADS][APAD];
    __shared__ float Ks[NHEADS][APAD];
    __shared__ float Vs[NHEADS][APAD];
    __shared__ float Ss[NHEADS][NHEADS];
    __shared__ float At[NHEADS][NHEADS];

    {
        const float4* q4 = (const float4*)(Q + (size_t)pos * DM);
        const float4* k4 = (const float4*)(K + (size_t)pos * DM);
        const float4* v4 = (const float4*)(V + (size_t)pos * DM);
        int hh = tid >> 4, dq = tid & 15;
        *(float4*)&Qs[hh][dq * 4] = q4[tid];
        *(float4*)&Ks[hh][dq * 4] = k4[tid];
        *(float4*)&Vs[hh][dq * 4] = v4[tid];
    }
    __syncthreads();

    {
        int h = tid >> 4, g = tid & 15;
        float s = 0.f;
#pragma unroll
        for (int d4 = 0; d4 < 16; d4++) {
            float4 qv = *(const float4*)&Qs[h][d4 * 4];
            float4 kv = *(const float4*)&Ks[g][d4 * 4];
            s += qv.x * kv.x + qv.y * kv.y + qv.z * kv.z + qv.w * kv.w;
        }
        Ss[h][g] = s * (1.0f / 12.0f);   // 1/(sqrt(64)*alpha)
    }
    __syncthreads();

    if (tid < NHEADS) {
        float z[16], zs[16], cum[16];
#pragma unroll
        for (int g = 0; g < 16; g++) { z[g] = Ss[tid][g]; zs[g] = z[g]; }
        for (int i = 1; i < 16; i++) {
            float key = zs[i];
            int j = i - 1;
            while (j >= 0 && zs[j] < key) { zs[j + 1] = zs[j]; j--; }
            zs[j + 1] = key;
        }
        float c = 0.f;
        int cnt = 0;
        for (int i = 0; i < 16; i++) {
            c += zs[i];
            cum[i] = c;
            if (zs[i] - (c - 1.0f) / (float)(i + 1) > 0.f) cnt++;
        }
        if (cnt < 1) cnt = 1;
        float tau = (cum[cnt - 1] - 1.0f) / (float)cnt;
#pragma unroll
        for (int g = 0; g < 16; g++) At[tid][g] = fmaxf(z[g] - tau, 0.f);
    }
    __syncthreads();

    {
        int hh = tid >> 4, dq = tid & 15;
        float4 o = make_float4(0.f, 0.f, 0.f, 0.f);
#pragma unroll
        for (int g = 0; g < 16; g++) {
            float wgt = At[hh][g];
            float4 vv = *(const float4*)&Vs[g][dq * 4];
            o.x += wgt * vv.x; o.y += wgt * vv.y; o.z += wgt * vv.z; o.w += wgt * vv.w;
        }
        const size_t xbase = (size_t)b * SEQA * DM + (size_t)(a >> 4) * DM
                           + (size_t)(a & 15) * HD;
        *(float4*)&X[xbase + (size_t)hh * 256 * DM + dq * 4] = o;
    }
}

// ---------------- launch ----------------
extern "C" void kernel_launch(void* const* d_in, const int* in_sizes, int n_in,
                              void* d_out, int out_size)
{
    const float* query = (const float*)d_in[0];
    const float* key   = (const float*)d_in[1];
    const float* value = (const float*)d_in[2];
    const float* Wq = (const float*)d_in[3];
    const float* bq = (const float*)d_in[4];
    const float* Wk = (const float*)d_in[5];
    const float* bk = (const float*)d_in[6];
    const float* Wv = (const float*)d_in[7];
    const float* bv = (const float*)d_in[8];
    const float* Wo = (const float*)d_in[9];
    const float* bo = (const float*)d_in[10];
    float* out = (float*)d_out;

    float *pQ, *pK, *pV, *pX;
    cudaGetSymbolAddress((void**)&pQ, g_Q);
    cudaGetSymbolAddress((void**)&pK, g_K);
    cudaGetSymbolAddress((void**)&pV, g_V);
    cudaGetSymbolAddress((void**)&pX, g_X);

    cudaFuncSetAttribute(gemm_qkv, cudaFuncAttributeMaxDynamicSharedMemorySize,
                         GEMM_SMEM);
    cudaFuncSetAttribute(gemm_out, cudaFuncAttributeMaxDynamicSharedMemorySize,
                         GEMM_SMEM);

    dim3 gq(DM / BN, MROWS / BM, 3);   // (8, 256, 3) — QKV in one launch
    gemm_qkv<<<gq, 512, GEMM_SMEM>>>(query, key, value,
                                     Wq, Wk, Wv, bq, bk, bv,
                                     pQ, pK, pV);
    attn_kernel<<<MROWS, 256>>>(pQ, pK, pV, pX);
    dim3 go(DM / BN, MROWS / BM);      // (8, 256)
    gemm_out<<<go, 512, GEMM_SMEM>>>(pX, Wo, bo, out);
}